// round 14
// baseline (speedup 1.0000x reference)
#include <cuda_runtime.h>
#include <cuda_bf16.h>
#include <stdint.h>

#define NT 128
#define TILE 128
#define KC 8
#define NCHUNK 4

// Precomputed per-lane B fragments: Bfrag[ks(12)][hl(2)][r(2)][nt(4)][lane(32)]
__device__ unsigned Bfrag_g[12 * 2 * 2 * 4 * 32];

__device__ __forceinline__ float P_val(const float* __restrict__ sig,
                                       const float* __restrict__ W,
                                       int kj, int o) {
    if (o >= 31) return 0.0f;
    int k = kj / 6, j = kj - 6 * k;
    float s = sig[k], s2 = s * s;
    float is2 = 1.0f / (s2 + 1e-6f);
    float is4 = 1.0f / (s2 * s2 + 1e-6f);
    const float* Wk = W + k * 186 + o;          // [k][h][o], H=6, O=31
    if (j == 0) return Wk[0] - is2 * (Wk[93] + Wk[155]);
    if (j == 1) return -is2 * Wk[62];           // * g*dx
    if (j == 2) return -is2 * Wk[31];           // * g*dy
    if (j == 3) return is4 * Wk[155];           // * g*dx^2
    if (j == 4) return is4 * Wk[124];           // * g*dx*dy
    return is4 * Wk[93];                        // * g*dy^2
}

__global__ void hermite_prep(const float* __restrict__ sig,
                             const float* __restrict__ W) {
    int i = blockIdx.x * blockDim.x + threadIdx.x;
    if (i >= 6144) return;
    int lane = i & 31;
    int nt   = (i >> 5) & 3;
    int r    = (i >> 7) & 1;
    int hl   = (i >> 8) & 1;
    int ks   = i >> 9;
    int g = lane >> 2, t = lane & 3;
    int n  = nt * 8 + g;                         // output column o
    int k0 = ks * 16 + r * 8 + 2 * t;            // kj index (k dim of mma)
    float va = P_val(sig, W, k0, n);
    float vb = P_val(sig, W, k0 + 1, n);
    unsigned ua = __float_as_uint(va), ub = __float_as_uint(vb);
    unsigned o32;
    if (hl == 0) {
        o32 = __byte_perm(ua, ub, 0x7632);       // bf16 hi parts, low=k-even
    } else {
        float la = va - __uint_as_float(ua & 0xFFFF0000u);
        float lb = vb - __uint_as_float(ub & 0xFFFF0000u);
        __nv_bfloat162 p = __floats2bfloat162_rn(la, lb);
        o32 = *reinterpret_cast<unsigned*>(&p);
    }
    Bfrag_g[i] = o32;
}

// ---- SMEM layout (words) ----
// raw: dxs[8][128], dys, gs -> 3*1024
// T: 24 pair-rows x 264 words; group gidx(pt)=((pt>>4)*8+(pt&7)) of 4 words:
//    {hi(pt),lo(pt),hi(pt+8),lo(pt+8)}  (stride 264 ≡ 8 mod 32, conflict-free)
#define RAWW 1024
#define T_OFF 3072
#define T_S   264
#define SMEM_WORDS (T_OFF + 24 * T_S)    // 9408 words = 37632 B

extern __shared__ __align__(16) float smem[];

__device__ __forceinline__ void mma_bf16(float& d0, float& d1, float& d2, float& d3,
                                         unsigned a0, unsigned a1, unsigned a2, unsigned a3,
                                         unsigned b0, unsigned b1) {
    asm volatile(
        "mma.sync.aligned.m16n8k16.row.col.f32.bf16.bf16.f32 "
        "{%0,%1,%2,%3}, {%4,%5,%6,%7}, {%8,%9}, {%0,%1,%2,%3};"
        : "+f"(d0), "+f"(d1), "+f"(d2), "+f"(d3)
        : "r"(a0), "r"(a1), "r"(a2), "r"(a3), "r"(b0), "r"(b1));
}

__global__ void __launch_bounds__(NT, 5)
hermite_main(const float* __restrict__ mlp,
             const float* __restrict__ cd,
             const float* __restrict__ gw,
             float* __restrict__ out,
             int total) {
    float* dxs = smem;
    float* dys = smem + RAWW;
    float* gs  = smem + 2 * RAWW;
    unsigned* T = reinterpret_cast<unsigned*>(smem + T_OFF);

    const int tid   = threadIdx.x;
    const int wid   = tid >> 5;       // m-quarter: pts [32wid, 32wid+32)
    const int lane  = tid & 31;
    const int g     = lane >> 2;
    const int t     = lane & 3;
    const int tile0 = blockIdx.x * TILE;
    // this thread's T write slot: gidx(tid)*4 + 2*((tid>>3)&1)
    const int wslot = ((tid >> 4) * 8 + (tid & 7)) * 4 + 2 * ((tid >> 3) & 1);

    float acc[2][4][4];
#pragma unroll
    for (int mi = 0; mi < 2; mi++)
#pragma unroll
        for (int ni = 0; ni < 4; ni++)
#pragma unroll
            for (int q = 0; q < 4; q++) acc[mi][ni][q] = 0.0f;

#pragma unroll 1
    for (int c = 0; c < NCHUNK; c++) {
        __syncthreads();   // previous chunk's T reads done

        // ---- Phase 1: coalesced raw staging (lane->kl fastest) ----
#pragma unroll
        for (int it = 0; it < 8; it++) {
            int item = tid + it * NT;
            int kl   = item & 7;
            int pt   = item >> 3;
            int n    = tile0 + pt;
            int k    = c * KC + kl;
            float dx = 0.0f, dy = 0.0f, gg = 0.0f;
            if (n < total) {
                float2 cc = reinterpret_cast<const float2*>(cd)[(size_t)n * 32 + k];
                dx = cc.x; dy = cc.y;
                gg = gw[(size_t)n * 32 + k];
            }
            int col = pt ^ ((pt & 32) >> 3) ^ (kl << 2);
            dxs[kl * TILE + col] = dx;
            dys[kl * TILE + col] = dy;
            gs [kl * TILE + col] = gg;
        }
        __syncthreads();

        // ---- Monomials -> bf16 {hi,lo} STS.64 into T (thread = pt) ----
#pragma unroll
        for (int kl = 0; kl < KC; kl++) {
            int col = kl * TILE + (tid ^ ((tid & 32) >> 3) ^ (kl << 2));
            float dx = dxs[col], dy = dys[col], gg = gs[col];
            float m1 = gg * dx, m2 = gg * dy;
            float m3 = m1 * dx, m4 = m1 * dy, m5 = m2 * dy;
            float pa[3] = { gg, m2, m4 };   // kj even of each pair
            float pb[3] = { m1, m3, m5 };   // kj odd
#pragma unroll
            for (int u = 0; u < 3; u++) {
                unsigned ua = __float_as_uint(pa[u]);
                unsigned ub = __float_as_uint(pb[u]);
                unsigned hi32 = __byte_perm(ua, ub, 0x7632);
                float la = pa[u] - __uint_as_float(ua & 0xFFFF0000u);
                float lb = pb[u] - __uint_as_float(ub & 0xFFFF0000u);
                __nv_bfloat162 p = __floats2bfloat162_rn(la, lb);
                uint2 w = make_uint2(hi32, *reinterpret_cast<unsigned*>(&p));
                *reinterpret_cast<uint2*>(&T[(3 * kl + u) * T_S + wslot]) = w;
            }
        }
        __syncthreads();

        // ---- MMA sweep: 3 k-steps x 2 m-tiles x 4 n-tiles x 3 passes ----
#pragma unroll
        for (int ksl = 0; ksl < 3; ksl++) {
            int ks = c * 3 + ksl;
            unsigned bh[4][2], bl[4][2];
#pragma unroll
            for (int ni = 0; ni < 4; ni++)
#pragma unroll
                for (int r = 0; r < 2; r++) {
                    bh[ni][r] = __ldg(&Bfrag_g[(((ks * 2 + 0) * 2 + r) * 4 + ni) * 32 + lane]);
                    bl[ni][r] = __ldg(&Bfrag_g[(((ks * 2 + 1) * 2 + r) * 4 + ni) * 32 + lane]);
                }
            int rowA = (8 * ksl + t) * T_S;
#pragma unroll
            for (int mi = 0; mi < 2; mi++) {
                int gb = ((2 * wid + mi) * 8 + g) * 4;
                // {hi(pt), lo(pt), hi(pt+8), lo(pt+8)} for pair cols t, t+4
                uint4 A1 = *reinterpret_cast<const uint4*>(&T[rowA + gb]);
                uint4 A2 = *reinterpret_cast<const uint4*>(&T[rowA + 4 * T_S + gb]);
#pragma unroll
                for (int ni = 0; ni < 4; ni++) {
                    float* d = acc[mi][ni];
                    mma_bf16(d[0], d[1], d[2], d[3], A1.x, A1.z, A2.x, A2.z,
                             bh[ni][0], bh[ni][1]);
                    mma_bf16(d[0], d[1], d[2], d[3], A1.x, A1.z, A2.x, A2.z,
                             bl[ni][0], bl[ni][1]);
                    mma_bf16(d[0], d[1], d[2], d[3], A1.y, A1.w, A2.y, A2.w,
                             bh[ni][0], bh[ni][1]);
                }
            }
        }
    }

    // ---- Epilogue: fragments -> stage[128][33] -> coalesced out = mlp*mix ----
    __syncthreads();
    float* stage = smem;              // 4224 words <= 9408
#pragma unroll
    for (int mi = 0; mi < 2; mi++) {
        int row0 = 32 * wid + mi * 16 + g;
#pragma unroll
        for (int ni = 0; ni < 4; ni++) {
            int o0 = ni * 8 + 2 * t;
            stage[row0 * 33 + o0]           = acc[mi][ni][0];
            stage[row0 * 33 + o0 + 1]       = acc[mi][ni][1];
            stage[(row0 + 8) * 33 + o0]     = acc[mi][ni][2];
            stage[(row0 + 8) * 33 + o0 + 1] = acc[mi][ni][3];
        }
    }
    __syncthreads();

    size_t lim  = (size_t)total * 31;
    size_t base = (size_t)tile0 * 31;
    for (int e = tid; e < TILE * 31; e += NT) {
        size_t gidx = base + e;
        if (gidx < lim) {
            int rr = e / 31;
            int o  = e - rr * 31;
            out[gidx] = mlp[gidx] * stage[rr * 33 + o];
        }
    }
}

extern "C" void kernel_launch(void* const* d_in, const int* in_sizes, int n_in,
                              void* d_out, int out_size) {
    const float* mlp = (const float*)d_in[0];  // [B,N,31]
    const float* cd  = (const float*)d_in[1];  // [B,N,32,2]
    const float* sig = (const float*)d_in[2];  // [32]
    const float* gw  = (const float*)d_in[3];  // [B,N,32]
    const float* W   = (const float*)d_in[4];  // [32,6,31]

    int total  = in_sizes[3] / 32;             // B*N = 262144
    int blocks = (total + TILE - 1) / TILE;    // 2048

    hermite_prep<<<(6144 + 255) / 256, 256>>>(sig, W);

    cudaFuncSetAttribute(hermite_main,
                         cudaFuncAttributeMaxDynamicSharedMemorySize,
                         SMEM_WORDS * 4);
    hermite_main<<<blocks, NT, SMEM_WORDS * 4>>>(mlp, cd, gw, (float*)d_out, total);
}